// round 6
// baseline (speedup 1.0000x reference)
#include <cuda_runtime.h>
#include <math.h>

// Shapes (hardcoded per reference)
#define V  32
#define B  128
#define P  256
#define J  75
#define S2 25
#define F1 500   // fc1 out
#define F2 200   // fc2 out
#define KX 800   // V*S2

// Scratch (device globals: no allocation allowed). Batch-major activations.
__device__ float g_z [V*B*J];                       // SLayer output
__device__ __align__(16) float g_x [B*KX];          // concat acts, [b][k]
__device__ __align__(16) float g_y1[B*F1];          // fc1 post-BN, [b][f]

__device__ __forceinline__ float warpSum(float v) {
    #pragma unroll
    for (int o = 16; o > 0; o >>= 1) v += __shfl_down_sync(0xffffffffu, v, o);
    return v;
}

// ---------------------------------------------------------------------------
// Kernel 1: transform + SLayer. One block per (v, b-pair). blockDim = 160.
// (proven R2 version, verbatim)
__global__ void k_slayer(const float* __restrict__ births, const float* __restrict__ lifetimes,
                         const int* __restrict__ mask, const float* __restrict__ centers,
                         const float* __restrict__ sharpness) {
    int blk = blockIdx.x;           // V * B/2 = 2048
    int v   = blk >> 6;
    int b0  = (blk & 63) << 1;
    __shared__ float sqx[2][P], sqy[2][P];
    __shared__ int scnt[2];
    int tid = threadIdx.x;

    if (tid < 64) {
        int w = tid >> 5, lane = tid & 31;
        int base = (v*B + b0 + w) * P;
        int cnt = 0;
        #pragma unroll
        for (int c = 0; c < P/32; ++c) {
            int p = c*32 + lane;
            int mv = mask[base + p];
            float bb = births[base + p], ll = lifetimes[base + p];
            float dd = bb + ll + 0.01f;
            const float inv = 0.70710678118654752440f;
            float x = (bb + dd) * inv;
            float y = (dd - bb) * inv;
            if (y <= 0.1f) y = __logf(y * 10.0f) * 0.1f + 0.1f;
            unsigned bal = __ballot_sync(0xffffffffu, mv != 0);
            if (mv) {
                int pos = cnt + __popc(bal & ((1u << lane) - 1u));
                sqx[w][pos] = x; sqy[w][pos] = y;
            }
            cnt += __popc(bal);
        }
        if (lane == 0) scnt[w] = cnt;
    }
    __syncthreads();

    if (tid < 2*J) {
        int w = (tid >= J);
        int j = tid - w*J;
        int n = scnt[w];
        int cj = (v*J + j) * 2;
        float cx = centers[cj], cy = centers[cj+1];
        float sx = sharpness[cj];   sx *= sx;
        float sy = sharpness[cj+1]; sy *= sy;
        float acc = 0.f;
        for (int p = 0; p < n; ++p) {
            float dx = sqx[w][p] - cx;
            float dy = sqy[w][p] - cy;
            float d2 = fmaf(sx*dx, dx, sy*dy*dy);
            acc += __expf(-d2);
        }
        g_z[(v*B + b0 + w)*J + j] = acc;
    }
}

// ---------------------------------------------------------------------------
// Kernel 2: prew + neighbor stack + stage_1(max) + l1 + BN1 + l2 + ReLU.
// One block per v. blockDim = 512. (R2 version; only final store layout changed.)
__global__ void k_mid(const float* __restrict__ w1, const float* __restrict__ w2,
                      const float* __restrict__ l1_w, const float* __restrict__ l1_b,
                      const float* __restrict__ bn1_g, const float* __restrict__ bn1_b,
                      const float* __restrict__ l2_w, const float* __restrict__ l2_b) {
    int v = blockIdx.x;
    __shared__ float sW[24];
    __shared__ float hh[64*J];       // 19.2 KB (half-batch staging)
    __shared__ float su[B*S2];       // 12.8 KB
    __shared__ float sl1[S2*J];      // 7.5 KB
    __shared__ float sl2[S2*S2];     // 2.5 KB
    __shared__ float smean[S2], sscale[S2], sbeta[S2], sb1[S2], sb2[S2];
    int tid = threadIdx.x;

    if (tid < 24) {                  // fused stage_1 weights: W = w2 @ w1
        int g = tid/3, c = tid%3;
        float acc = 0.f;
        #pragma unroll 8
        for (int f = 0; f < 32; ++f)
            acc = fmaf(w2[(v*8+g)*32 + f], w1[(v*32+f)*3 + c], acc);
        sW[tid] = acc;
    }
    for (int i = tid; i < S2*J;  i += 512) sl1[i] = l1_w[v*S2*J  + i];
    for (int i = tid; i < S2*S2; i += 512) sl2[i] = l2_w[v*S2*S2 + i];
    if (tid < S2) { sb1[tid] = l1_b[v*S2+tid]; sb2[tid] = l2_b[v*S2+tid]; sbeta[tid] = bn1_b[v*S2+tid]; }
    __syncthreads();

    int vm = (v + V - 1) & (V - 1), vp = (v + 1) & (V - 1);
    for (int half = 0; half < 2; ++half) {
        int bb0 = half * 64;
        for (int i = tid; i < 64*J; i += 512) {
            int bl = i / J, j = i % J, b = bb0 + bl;
            float z0 = g_z[(vm*B + b)*J + j];
            float z1 = g_z[(v *B + b)*J + j];
            float z2 = g_z[(vp*B + b)*J + j];
            float m = -INFINITY;
            #pragma unroll
            for (int g = 0; g < 8; ++g) {
                float s = fmaf(sW[g*3+2], z2, fmaf(sW[g*3+1], z1, sW[g*3]*z0));
                m = fmaxf(m, s);
            }
            hh[i] = m;
        }
        __syncthreads();
        for (int i = tid; i < S2*64; i += 512) {
            int o = i / 64, bl = i % 64;
            float acc = sb1[o];
            const float* hr = &hh[bl*J];
            const float* wr = &sl1[o*J];
            #pragma unroll 5
            for (int j = 0; j < J; ++j) acc = fmaf(hr[j], wr[j], acc);
            su[(bb0 + bl)*S2 + o] = acc;
        }
        __syncthreads();
    }

    // BN1 stats: one warp per output channel
    int warp = tid >> 5, lane = tid & 31;
    for (int o = warp; o < S2; o += 16) {
        float s = 0.f;
        #pragma unroll
        for (int b = lane; b < B; b += 32) s += su[b*S2 + o];
        s = warpSum(s);
        s = __shfl_sync(0xffffffffu, s, 0);
        float mean = s * (1.f / B);
        float vv = 0.f;
        #pragma unroll
        for (int b = lane; b < B; b += 32) { float d = su[b*S2 + o] - mean; vv = fmaf(d, d, vv); }
        vv = warpSum(vv);
        if (lane == 0) { smean[o] = mean; sscale[o] = bn1_g[v*S2+o] * rsqrtf(vv*(1.f/B) + 1e-5f); }
    }
    __syncthreads();

    for (int i = tid; i < B*S2; i += 512) {
        int o = i % S2;
        su[i] = (su[i] - smean[o]) * sscale[o] + sbeta[o];
    }
    __syncthreads();

    // l2 + ReLU, write batch-major x[b][v*S2 + p]
    for (int i = tid; i < S2*B; i += 512) {
        int p = i / B, b = i % B;
        float acc = sb2[p];
        const float* ur = &su[b*S2];
        const float* wr = &sl2[p*S2];
        #pragma unroll
        for (int o = 0; o < S2; ++o) acc = fmaf(ur[o], wr[o], acc);
        g_x[b*KX + v*S2 + p] = fmaxf(acc, 0.f);
    }
}

// ---------------------------------------------------------------------------
// Kernel 3: fc1 (800->500) + BN2. 5 features/block, 8-way k-split in-block.
// grid = 100, blockDim = 1024. Thread bb streams its contiguous x row with
// float4 LDG.128 (chunks c == ks mod 8 of 200 total).
#define FPB 5
__global__ void __launch_bounds__(1024, 1)
k_fc1(const float* __restrict__ fc1_w, const float* __restrict__ fc1_b,
      const float* __restrict__ bn2_g, const float* __restrict__ bn2_b) {
    __shared__ __align__(16) float sw[FPB*KX];   // 16 KB, [ff][k]
    __shared__ float part[8*FPB*B];              // 20 KB
    __shared__ float smean[FPB], sscale[FPB];
    int f0 = blockIdx.x * FPB;
    int tid = threadIdx.x;
    int ks = tid >> 7, bb = tid & 127;           // ks in 0..7

    for (int i = tid; i < FPB*KX; i += 1024) sw[i] = fc1_w[f0*KX + i];
    __syncthreads();

    float acc[FPB];
    #pragma unroll
    for (int ff = 0; ff < FPB; ++ff) acc[ff] = (ks == 0) ? fc1_b[f0+ff] : 0.f;
    const float4* xb = reinterpret_cast<const float4*>(g_x + bb*KX);
    const float4* w4 = reinterpret_cast<const float4*>(sw);
    for (int c = ks; c < 200; c += 8) {          // 25 float4 chunks per thread
        float4 xv = xb[c];
        #pragma unroll
        for (int ff = 0; ff < FPB; ++ff) {
            float4 wv = w4[ff*200 + c];
            acc[ff] = fmaf(xv.x, wv.x, acc[ff]);
            acc[ff] = fmaf(xv.y, wv.y, acc[ff]);
            acc[ff] = fmaf(xv.z, wv.z, acc[ff]);
            acc[ff] = fmaf(xv.w, wv.w, acc[ff]);
        }
    }
    #pragma unroll
    for (int ff = 0; ff < FPB; ++ff) part[(ks*FPB + ff)*B + bb] = acc[ff];
    __syncthreads();
    if (ks < 4) {
        #pragma unroll
        for (int ff = 0; ff < FPB; ++ff)
            part[(ks*FPB + ff)*B + bb] += part[((ks+4)*FPB + ff)*B + bb];
    }
    __syncthreads();
    if (ks < 2) {
        #pragma unroll
        for (int ff = 0; ff < FPB; ++ff)
            part[(ks*FPB + ff)*B + bb] += part[((ks+2)*FPB + ff)*B + bb];
    }
    __syncthreads();
    if (ks == 0) {
        #pragma unroll
        for (int ff = 0; ff < FPB; ++ff)
            part[ff*B + bb] += part[(FPB + ff)*B + bb];
    }
    __syncthreads();

    // BN2 stats: warp ff reduces feature ff over batch
    int warp = tid >> 5, lane = tid & 31;
    if (warp < FPB) {
        float s = 0.f;
        #pragma unroll
        for (int b = lane; b < B; b += 32) s += part[warp*B + b];
        s = warpSum(s);
        s = __shfl_sync(0xffffffffu, s, 0);
        float mean = s * (1.f / B);
        float vv = 0.f;
        #pragma unroll
        for (int b = lane; b < B; b += 32) { float d = part[warp*B + b] - mean; vv = fmaf(d, d, vv); }
        vv = warpSum(vv);
        if (lane == 0) { smean[warp] = mean; sscale[warp] = bn2_g[f0+warp] * rsqrtf(vv*(1.f/B) + 1e-5f); }
    }
    __syncthreads();

    if (ks == 0) {
        #pragma unroll
        for (int ff = 0; ff < FPB; ++ff)
            g_y1[bb*F1 + f0 + ff] = (part[ff*B + bb] - smean[ff]) * sscale[ff] + bn2_b[f0+ff];
    }
}

// ---------------------------------------------------------------------------
// Kernel 4: fc2 (500->200). 2 outputs/block, 4-way interleaved k-split.
// grid = 100, blockDim = 512. Thread bb streams its contiguous y row with
// float4 (chunks c == ks mod 4 of 125 total), 2-deep manual pipelining.
#define OPB 2
__global__ void __launch_bounds__(512, 2)
k_fc2(const float* __restrict__ fc2_w, const float* __restrict__ fc2_b,
      float* __restrict__ out) {
    __shared__ __align__(16) float sw[OPB*F1];   // 4 KB
    __shared__ float part[4*OPB*B];              // 4 KB
    int o0 = blockIdx.x * OPB;
    int tid = threadIdx.x;
    int ks = tid >> 7, bb = tid & 127;           // ks in 0..3

    for (int i = tid; i < OPB*F1; i += 512) sw[i] = fc2_w[o0*F1 + i];
    __syncthreads();

    float a0 = (ks == 0) ? fc2_b[o0]   : 0.f;
    float a1 = (ks == 0) ? fc2_b[o0+1] : 0.f;
    const float4* yb = reinterpret_cast<const float4*>(g_y1 + bb*F1);
    const float4* w0 = reinterpret_cast<const float4*>(sw);
    const float4* w1 = reinterpret_cast<const float4*>(sw + F1);
    int c = ks;
    for (; c + 4 < 125; c += 8) {                // two independent chunks in flight
        float4 ya = yb[c], yc = yb[c+4];
        float4 wa0 = w0[c],   wa1 = w1[c];
        float4 wc0 = w0[c+4], wc1 = w1[c+4];
        a0 = fmaf(ya.x, wa0.x, a0); a1 = fmaf(ya.x, wa1.x, a1);
        a0 = fmaf(ya.y, wa0.y, a0); a1 = fmaf(ya.y, wa1.y, a1);
        a0 = fmaf(ya.z, wa0.z, a0); a1 = fmaf(ya.z, wa1.z, a1);
        a0 = fmaf(ya.w, wa0.w, a0); a1 = fmaf(ya.w, wa1.w, a1);
        a0 = fmaf(yc.x, wc0.x, a0); a1 = fmaf(yc.x, wc1.x, a1);
        a0 = fmaf(yc.y, wc0.y, a0); a1 = fmaf(yc.y, wc1.y, a1);
        a0 = fmaf(yc.z, wc0.z, a0); a1 = fmaf(yc.z, wc1.z, a1);
        a0 = fmaf(yc.w, wc0.w, a0); a1 = fmaf(yc.w, wc1.w, a1);
    }
    if (c < 125) {
        float4 ya = yb[c];
        float4 wa0 = w0[c], wa1 = w1[c];
        a0 = fmaf(ya.x, wa0.x, a0); a1 = fmaf(ya.x, wa1.x, a1);
        a0 = fmaf(ya.y, wa0.y, a0); a1 = fmaf(ya.y, wa1.y, a1);
        a0 = fmaf(ya.z, wa0.z, a0); a1 = fmaf(ya.z, wa1.z, a1);
        a0 = fmaf(ya.w, wa0.w, a0); a1 = fmaf(ya.w, wa1.w, a1);
    }
    part[(ks*OPB + 0)*B + bb] = a0;
    part[(ks*OPB + 1)*B + bb] = a1;
    __syncthreads();
    if (ks < 2) {
        #pragma unroll
        for (int oo = 0; oo < OPB; ++oo)
            part[(ks*OPB + oo)*B + bb] += part[((ks+2)*OPB + oo)*B + bb];
    }
    __syncthreads();
    if (ks == 0) {
        out[bb*F2 + o0 + 0] = part[0*B + bb] + part[(OPB+0)*B + bb];
        out[bb*F2 + o0 + 1] = part[1*B + bb] + part[(OPB+1)*B + bb];
    }
}

// ---------------------------------------------------------------------------
extern "C" void kernel_launch(void* const* d_in, const int* in_sizes, int n_in,
                              void* d_out, int out_size) {
    const float* births    = (const float*)d_in[0];
    const float* lifetimes = (const float*)d_in[1];
    const int*   mask      = (const int*)  d_in[2];
    const float* centers   = (const float*)d_in[3];
    const float* sharpness = (const float*)d_in[4];
    const float* w1        = (const float*)d_in[5];
    const float* w2        = (const float*)d_in[6];
    const float* l1_w      = (const float*)d_in[7];
    const float* l1_b      = (const float*)d_in[8];
    const float* bn1_g     = (const float*)d_in[9];
    const float* bn1_b     = (const float*)d_in[10];
    const float* l2_w      = (const float*)d_in[11];
    const float* l2_b      = (const float*)d_in[12];
    const float* fc1_w     = (const float*)d_in[13];
    const float* fc1_b     = (const float*)d_in[14];
    const float* bn2_g     = (const float*)d_in[15];
    const float* bn2_b     = (const float*)d_in[16];
    const float* fc2_w     = (const float*)d_in[17];
    const float* fc2_b     = (const float*)d_in[18];
    float* out = (float*)d_out;

    k_slayer<<<V*B/2, 160>>>(births, lifetimes, mask, centers, sharpness);
    k_mid   <<<V, 512>>>(w1, w2, l1_w, l1_b, bn1_g, bn1_b, l2_w, l2_b);
    k_fc1   <<<F1/FPB, 1024>>>(fc1_w, fc1_b, bn2_g, bn2_b);
    k_fc2   <<<F2/OPB, 512>>>(fc2_w, fc2_b, out);
}

// round 8
// speedup vs baseline: 1.1718x; 1.1718x over previous
#include <cuda_runtime.h>
#include <math.h>

// Shapes (hardcoded per reference)
#define V  32
#define B  128
#define P  256
#define J  75
#define S2 25
#define F1 500   // fc1 out
#define F2 200   // fc2 out
#define KX 800   // V*S2

// Scratch (device globals). k-major activations: coalesced across batch.
__device__ float g_z [V*B*J];                        // SLayer output
__device__ __align__(16) float g_xT[KX*B];           // concat acts, [k][b]
__device__ __align__(16) float g_y1[F1*B];           // fc1 post-BN, [f][b]

__device__ __forceinline__ float warpSum(float v) {
    #pragma unroll
    for (int o = 16; o > 0; o >>= 1) v += __shfl_down_sync(0xffffffffu, v, o);
    return v;
}

// ---------------------------------------------------------------------------
// Kernel 1: transform + SLayer. One block per (v, b-pair). blockDim = 160.
// (proven R2 version, verbatim)
__global__ void k_slayer(const float* __restrict__ births, const float* __restrict__ lifetimes,
                         const int* __restrict__ mask, const float* __restrict__ centers,
                         const float* __restrict__ sharpness) {
    int blk = blockIdx.x;           // V * B/2 = 2048
    int v   = blk >> 6;
    int b0  = (blk & 63) << 1;
    __shared__ float sqx[2][P], sqy[2][P];
    __shared__ int scnt[2];
    int tid = threadIdx.x;

    if (tid < 64) {
        int w = tid >> 5, lane = tid & 31;
        int base = (v*B + b0 + w) * P;
        int cnt = 0;
        #pragma unroll
        for (int c = 0; c < P/32; ++c) {
            int p = c*32 + lane;
            int mv = mask[base + p];
            float bb = births[base + p], ll = lifetimes[base + p];
            float dd = bb + ll + 0.01f;
            const float inv = 0.70710678118654752440f;
            float x = (bb + dd) * inv;
            float y = (dd - bb) * inv;
            if (y <= 0.1f) y = __logf(y * 10.0f) * 0.1f + 0.1f;
            unsigned bal = __ballot_sync(0xffffffffu, mv != 0);
            if (mv) {
                int pos = cnt + __popc(bal & ((1u << lane) - 1u));
                sqx[w][pos] = x; sqy[w][pos] = y;
            }
            cnt += __popc(bal);
        }
        if (lane == 0) scnt[w] = cnt;
    }
    __syncthreads();

    if (tid < 2*J) {
        int w = (tid >= J);
        int j = tid - w*J;
        int n = scnt[w];
        int cj = (v*J + j) * 2;
        float cx = centers[cj], cy = centers[cj+1];
        float sx = sharpness[cj];   sx *= sx;
        float sy = sharpness[cj+1]; sy *= sy;
        float acc = 0.f;
        for (int p = 0; p < n; ++p) {
            float dx = sqx[w][p] - cx;
            float dy = sqy[w][p] - cy;
            float d2 = fmaf(sx*dx, dx, sy*dy*dy);
            acc += __expf(-d2);
        }
        g_z[(v*B + b0 + w)*J + j] = acc;
    }
}

// ---------------------------------------------------------------------------
// Kernel 2: prew + neighbor stack + stage_1(max) + l1 + BN1 + l2 + ReLU.
// One block per v. blockDim = 512. Writes k-major x[(v*S2+p)*B + b].
__global__ void k_mid(const float* __restrict__ w1, const float* __restrict__ w2,
                      const float* __restrict__ l1_w, const float* __restrict__ l1_b,
                      const float* __restrict__ bn1_g, const float* __restrict__ bn1_b,
                      const float* __restrict__ l2_w, const float* __restrict__ l2_b) {
    int v = blockIdx.x;
    __shared__ float sW[24];
    __shared__ float hh[64*J];       // 19.2 KB (half-batch staging)
    __shared__ float su[B*S2];       // 12.8 KB
    __shared__ float sl1[S2*J];      // 7.5 KB
    __shared__ float sl2[S2*S2];     // 2.5 KB
    __shared__ float smean[S2], sscale[S2], sbeta[S2], sb1[S2], sb2[S2];
    int tid = threadIdx.x;

    if (tid < 24) {                  // fused stage_1 weights: W = w2 @ w1
        int g = tid/3, c = tid%3;
        float acc = 0.f;
        #pragma unroll 8
        for (int f = 0; f < 32; ++f)
            acc = fmaf(w2[(v*8+g)*32 + f], w1[(v*32+f)*3 + c], acc);
        sW[tid] = acc;
    }
    for (int i = tid; i < S2*J;  i += 512) sl1[i] = l1_w[v*S2*J  + i];
    for (int i = tid; i < S2*S2; i += 512) sl2[i] = l2_w[v*S2*S2 + i];
    if (tid < S2) { sb1[tid] = l1_b[v*S2+tid]; sb2[tid] = l2_b[v*S2+tid]; sbeta[tid] = bn1_b[v*S2+tid]; }
    __syncthreads();

    int vm = (v + V - 1) & (V - 1), vp = (v + 1) & (V - 1);
    for (int half = 0; half < 2; ++half) {
        int bb0 = half * 64;
        for (int i = tid; i < 64*J; i += 512) {
            int bl = i / J, j = i % J, b = bb0 + bl;
            float z0 = g_z[(vm*B + b)*J + j];
            float z1 = g_z[(v *B + b)*J + j];
            float z2 = g_z[(vp*B + b)*J + j];
            float m = -INFINITY;
            #pragma unroll
            for (int g = 0; g < 8; ++g) {
                float s = fmaf(sW[g*3+2], z2, fmaf(sW[g*3+1], z1, sW[g*3]*z0));
                m = fmaxf(m, s);
            }
            hh[i] = m;
        }
        __syncthreads();
        for (int i = tid; i < S2*64; i += 512) {
            int o = i / 64, bl = i % 64;
            float acc = sb1[o];
            const float* hr = &hh[bl*J];
            const float* wr = &sl1[o*J];
            #pragma unroll 5
            for (int j = 0; j < J; ++j) acc = fmaf(hr[j], wr[j], acc);
            su[(bb0 + bl)*S2 + o] = acc;
        }
        __syncthreads();
    }

    // BN1 stats: one warp per output channel
    int warp = tid >> 5, lane = tid & 31;
    for (int o = warp; o < S2; o += 16) {
        float s = 0.f;
        #pragma unroll
        for (int b = lane; b < B; b += 32) s += su[b*S2 + o];
        s = warpSum(s);
        s = __shfl_sync(0xffffffffu, s, 0);
        float mean = s * (1.f / B);
        float vv = 0.f;
        #pragma unroll
        for (int b = lane; b < B; b += 32) { float d = su[b*S2 + o] - mean; vv = fmaf(d, d, vv); }
        vv = warpSum(vv);
        if (lane == 0) { smean[o] = mean; sscale[o] = bn1_g[v*S2+o] * rsqrtf(vv*(1.f/B) + 1e-5f); }
    }
    __syncthreads();

    for (int i = tid; i < B*S2; i += 512) {
        int o = i % S2;
        su[i] = (su[i] - smean[o]) * sscale[o] + sbeta[o];
    }
    __syncthreads();

    // l2 + ReLU, write k-major
    for (int i = tid; i < S2*B; i += 512) {
        int p = i / B, b = i % B;
        float acc = sb2[p];
        const float* ur = &su[b*S2];
        const float* wr = &sl2[p*S2];
        #pragma unroll
        for (int o = 0; o < S2; ++o) acc = fmaf(ur[o], wr[o], acc);
        g_xT[(v*S2 + p)*B + b] = fmaxf(acc, 0.f);
    }
}

// ---------------------------------------------------------------------------
// Kernel 3: fc1 (800->500) + BN2. grid=100, blockDim=256 (8 warps).
// Warp w = k-slice of 100. Lane l owns batches 4l..4l+3 (float4, coalesced).
#define FPB 5
__global__ void __launch_bounds__(256, 1)
k_fc1(const float* __restrict__ fc1_w, const float* __restrict__ fc1_b,
      const float* __restrict__ bn2_g, const float* __restrict__ bn2_b) {
    __shared__ float sw[FPB*KX];            // 16 KB
    __shared__ float part[8*FPB*B];         // 20 KB
    __shared__ float smean[FPB], sscale[FPB];
    int f0 = blockIdx.x * FPB;
    int tid = threadIdx.x;
    int w = tid >> 5, lane = tid & 31;

    for (int i = tid; i < FPB*KX; i += 256) sw[i] = fc1_w[f0*KX + i];
    __syncthreads();

    float acc[FPB][4];
    #pragma unroll
    for (int ff = 0; ff < FPB; ++ff) {
        float bv = (w == 0) ? fc1_b[f0+ff] : 0.f;   // bias to ALL batches of slice 0
        acc[ff][0] = bv; acc[ff][1] = bv; acc[ff][2] = bv; acc[ff][3] = bv;
    }
    const float4* x4 = reinterpret_cast<const float4*>(g_xT);  // [k][b/4]
    int k0 = w * 100;
    #pragma unroll 4
    for (int k = k0; k < k0 + 100; ++k) {
        float4 xv = x4[k*32 + lane];
        #pragma unroll
        for (int ff = 0; ff < FPB; ++ff) {
            float wv = sw[ff*KX + k];
            acc[ff][0] = fmaf(wv, xv.x, acc[ff][0]);
            acc[ff][1] = fmaf(wv, xv.y, acc[ff][1]);
            acc[ff][2] = fmaf(wv, xv.z, acc[ff][2]);
            acc[ff][3] = fmaf(wv, xv.w, acc[ff][3]);
        }
    }
    #pragma unroll
    for (int ff = 0; ff < FPB; ++ff) {
        #pragma unroll
        for (int u = 0; u < 4; ++u)
            part[(w*FPB + ff)*B + 4*lane + u] = acc[ff][u];
    }
    __syncthreads();
    // serial deterministic combine over the 8 k-slices
    for (int i = tid; i < FPB*B; i += 256) {
        float s = part[i];
        #pragma unroll
        for (int ks = 1; ks < 8; ++ks) s += part[ks*FPB*B + i];
        part[i] = s;
    }
    __syncthreads();

    // BN2 stats: warp ff reduces feature ff over batch
    if (w < FPB) {
        float s = 0.f;
        #pragma unroll
        for (int b = lane; b < B; b += 32) s += part[w*B + b];
        s = warpSum(s);
        s = __shfl_sync(0xffffffffu, s, 0);
        float mean = s * (1.f / B);
        float vv = 0.f;
        #pragma unroll
        for (int b = lane; b < B; b += 32) { float d = part[w*B + b] - mean; vv = fmaf(d, d, vv); }
        vv = warpSum(vv);
        if (lane == 0) { smean[w] = mean; sscale[w] = bn2_g[f0+w] * rsqrtf(vv*(1.f/B) + 1e-5f); }
    }
    __syncthreads();

    for (int i = tid; i < FPB*B; i += 256) {
        int ff = i / B, b = i % B;
        g_y1[(f0+ff)*B + b] = (part[i] - smean[ff]) * sscale[ff] + bn2_b[f0+ff];
    }
}

// ---------------------------------------------------------------------------
// Kernel 4: fc2 (500->200). grid=100, blockDim=256 (8 warps).
// Warp w = k-slice of ~63. Lane l owns batches 4l..4l+3 (float4, coalesced).
#define OPB 2
__global__ void __launch_bounds__(256, 1)
k_fc2(const float* __restrict__ fc2_w, const float* __restrict__ fc2_b,
      float* __restrict__ out) {
    __shared__ float sw[OPB*F1];            // 4 KB
    __shared__ float part[8*OPB*B];         // 8 KB
    int o0 = blockIdx.x * OPB;
    int tid = threadIdx.x;
    int w = tid >> 5, lane = tid & 31;

    for (int i = tid; i < OPB*F1; i += 256) sw[i] = fc2_w[o0*F1 + i];
    __syncthreads();

    float a0[4], a1[4];
    {
        float b0 = (w == 0) ? fc2_b[o0]   : 0.f;   // bias to ALL batches of slice 0
        float b1 = (w == 0) ? fc2_b[o0+1] : 0.f;
        a0[0]=b0; a0[1]=b0; a0[2]=b0; a0[3]=b0;
        a1[0]=b1; a1[1]=b1; a1[2]=b1; a1[3]=b1;
    }
    const float4* y4 = reinterpret_cast<const float4*>(g_y1);  // [f][b/4]
    int fs = (w * F1) / 8, fe = ((w + 1) * F1) / 8;
    #pragma unroll 4
    for (int f = fs; f < fe; ++f) {
        float4 yv = y4[f*32 + lane];
        float w0 = sw[f], w1 = sw[F1 + f];
        a0[0] = fmaf(w0, yv.x, a0[0]); a1[0] = fmaf(w1, yv.x, a1[0]);
        a0[1] = fmaf(w0, yv.y, a0[1]); a1[1] = fmaf(w1, yv.y, a1[1]);
        a0[2] = fmaf(w0, yv.z, a0[2]); a1[2] = fmaf(w1, yv.z, a1[2]);
        a0[3] = fmaf(w0, yv.w, a0[3]); a1[3] = fmaf(w1, yv.w, a1[3]);
    }
    #pragma unroll
    for (int u = 0; u < 4; ++u) {
        part[(w*OPB + 0)*B + 4*lane + u] = a0[u];
        part[(w*OPB + 1)*B + 4*lane + u] = a1[u];
    }
    __syncthreads();
    // serial combine + store
    for (int i = tid; i < OPB*B; i += 256) {
        float s = part[i];
        #pragma unroll
        for (int ks = 1; ks < 8; ++ks) s += part[ks*OPB*B + i];
        int oo = i / B, b = i % B;
        out[b*F2 + o0 + oo] = s;
    }
}

// ---------------------------------------------------------------------------
extern "C" void kernel_launch(void* const* d_in, const int* in_sizes, int n_in,
                              void* d_out, int out_size) {
    const float* births    = (const float*)d_in[0];
    const float* lifetimes = (const float*)d_in[1];
    const int*   mask      = (const int*)  d_in[2];
    const float* centers   = (const float*)d_in[3];
    const float* sharpness = (const float*)d_in[4];
    const float* w1        = (const float*)d_in[5];
    const float* w2        = (const float*)d_in[6];
    const float* l1_w      = (const float*)d_in[7];
    const float* l1_b      = (const float*)d_in[8];
    const float* bn1_g     = (const float*)d_in[9];
    const float* bn1_b     = (const float*)d_in[10];
    const float* l2_w      = (const float*)d_in[11];
    const float* l2_b      = (const float*)d_in[12];
    const float* fc1_w     = (const float*)d_in[13];
    const float* fc1_b     = (const float*)d_in[14];
    const float* bn2_g     = (const float*)d_in[15];
    const float* bn2_b     = (const float*)d_in[16];
    const float* fc2_w     = (const float*)d_in[17];
    const float* fc2_b     = (const float*)d_in[18];
    float* out = (float*)d_out;

    k_slayer<<<V*B/2, 160>>>(births, lifetimes, mask, centers, sharpness);
    k_mid   <<<V, 512>>>(w1, w2, l1_w, l1_b, bn1_g, bn1_b, l2_w, l2_b);
    k_fc1   <<<F1/FPB, 256>>>(fc1_w, fc1_b, bn2_g, bn2_b);
    k_fc2   <<<F2/OPB, 256>>>(fc2_w, fc2_b, out);
}

// round 9
// speedup vs baseline: 1.2929x; 1.1033x over previous
#include <cuda_runtime.h>
#include <math.h>

// Shapes (hardcoded per reference)
#define V  32
#define B  128
#define P  256
#define J  75
#define S2 25
#define F1 500   // fc1 out
#define F2 200   // fc2 out
#define KX 800   // V*S2

// Scratch (device globals). k-major activations: coalesced across batch.
__device__ float g_z [V*B*J];                        // SLayer output
__device__ __align__(16) float g_xT[KX*B];           // concat acts, [k][b]
__device__ __align__(16) float g_y1[F1*B];           // fc1 post-BN, [f][b]

__device__ __forceinline__ float warpSum(float v) {
    #pragma unroll
    for (int o = 16; o > 0; o >>= 1) v += __shfl_down_sync(0xffffffffu, v, o);
    return v;
}

// ---------------------------------------------------------------------------
// Kernel 1: transform + SLayer. One block per (v, b-pair). blockDim = 160.
// (proven R2 version, verbatim)
__global__ void k_slayer(const float* __restrict__ births, const float* __restrict__ lifetimes,
                         const int* __restrict__ mask, const float* __restrict__ centers,
                         const float* __restrict__ sharpness) {
    int blk = blockIdx.x;           // V * B/2 = 2048
    int v   = blk >> 6;
    int b0  = (blk & 63) << 1;
    __shared__ float sqx[2][P], sqy[2][P];
    __shared__ int scnt[2];
    int tid = threadIdx.x;

    if (tid < 64) {
        int w = tid >> 5, lane = tid & 31;
        int base = (v*B + b0 + w) * P;
        int cnt = 0;
        #pragma unroll
        for (int c = 0; c < P/32; ++c) {
            int p = c*32 + lane;
            int mv = mask[base + p];
            float bb = births[base + p], ll = lifetimes[base + p];
            float dd = bb + ll + 0.01f;
            const float inv = 0.70710678118654752440f;
            float x = (bb + dd) * inv;
            float y = (dd - bb) * inv;
            if (y <= 0.1f) y = __logf(y * 10.0f) * 0.1f + 0.1f;
            unsigned bal = __ballot_sync(0xffffffffu, mv != 0);
            if (mv) {
                int pos = cnt + __popc(bal & ((1u << lane) - 1u));
                sqx[w][pos] = x; sqy[w][pos] = y;
            }
            cnt += __popc(bal);
        }
        if (lane == 0) scnt[w] = cnt;
    }
    __syncthreads();

    if (tid < 2*J) {
        int w = (tid >= J);
        int j = tid - w*J;
        int n = scnt[w];
        int cj = (v*J + j) * 2;
        float cx = centers[cj], cy = centers[cj+1];
        float sx = sharpness[cj];   sx *= sx;
        float sy = sharpness[cj+1]; sy *= sy;
        float acc = 0.f;
        for (int p = 0; p < n; ++p) {
            float dx = sqx[w][p] - cx;
            float dy = sqy[w][p] - cy;
            float d2 = fmaf(sx*dx, dx, sy*dy*dy);
            acc += __expf(-d2);
        }
        g_z[(v*B + b0 + w)*J + j] = acc;
    }
}

// ---------------------------------------------------------------------------
// Kernel 2: prew + neighbor stack + stage_1(max) + l1 + BN1 + l2 + ReLU.
// One block per v. blockDim = 512. Writes k-major x[(v*S2+p)*B + b].
__global__ void k_mid(const float* __restrict__ w1, const float* __restrict__ w2,
                      const float* __restrict__ l1_w, const float* __restrict__ l1_b,
                      const float* __restrict__ bn1_g, const float* __restrict__ bn1_b,
                      const float* __restrict__ l2_w, const float* __restrict__ l2_b) {
    int v = blockIdx.x;
    __shared__ float sW[24];
    __shared__ float hh[64*J];       // 19.2 KB (half-batch staging)
    __shared__ float su[B*S2];       // 12.8 KB
    __shared__ float sl1[S2*J];      // 7.5 KB
    __shared__ float sl2[S2*S2];     // 2.5 KB
    __shared__ float smean[S2], sscale[S2], sbeta[S2], sb1[S2], sb2[S2];
    int tid = threadIdx.x;

    if (tid < 24) {                  // fused stage_1 weights: W = w2 @ w1
        int g = tid/3, c = tid%3;
        float acc = 0.f;
        #pragma unroll 8
        for (int f = 0; f < 32; ++f)
            acc = fmaf(w2[(v*8+g)*32 + f], w1[(v*32+f)*3 + c], acc);
        sW[tid] = acc;
    }
    for (int i = tid; i < S2*J;  i += 512) sl1[i] = l1_w[v*S2*J  + i];
    for (int i = tid; i < S2*S2; i += 512) sl2[i] = l2_w[v*S2*S2 + i];
    if (tid < S2) { sb1[tid] = l1_b[v*S2+tid]; sb2[tid] = l2_b[v*S2+tid]; sbeta[tid] = bn1_b[v*S2+tid]; }
    __syncthreads();

    int vm = (v + V - 1) & (V - 1), vp = (v + 1) & (V - 1);
    for (int half = 0; half < 2; ++half) {
        int bb0 = half * 64;
        for (int i = tid; i < 64*J; i += 512) {
            int bl = i / J, j = i % J, b = bb0 + bl;
            float z0 = g_z[(vm*B + b)*J + j];
            float z1 = g_z[(v *B + b)*J + j];
            float z2 = g_z[(vp*B + b)*J + j];
            float m = -INFINITY;
            #pragma unroll
            for (int g = 0; g < 8; ++g) {
                float s = fmaf(sW[g*3+2], z2, fmaf(sW[g*3+1], z1, sW[g*3]*z0));
                m = fmaxf(m, s);
            }
            hh[i] = m;
        }
        __syncthreads();
        for (int i = tid; i < S2*64; i += 512) {
            int o = i / 64, bl = i % 64;
            float acc = sb1[o];
            const float* hr = &hh[bl*J];
            const float* wr = &sl1[o*J];
            #pragma unroll 5
            for (int j = 0; j < J; ++j) acc = fmaf(hr[j], wr[j], acc);
            su[(bb0 + bl)*S2 + o] = acc;
        }
        __syncthreads();
    }

    // BN1 stats: one warp per output channel
    int warp = tid >> 5, lane = tid & 31;
    for (int o = warp; o < S2; o += 16) {
        float s = 0.f;
        #pragma unroll
        for (int b = lane; b < B; b += 32) s += su[b*S2 + o];
        s = warpSum(s);
        s = __shfl_sync(0xffffffffu, s, 0);
        float mean = s * (1.f / B);
        float vv = 0.f;
        #pragma unroll
        for (int b = lane; b < B; b += 32) { float d = su[b*S2 + o] - mean; vv = fmaf(d, d, vv); }
        vv = warpSum(vv);
        if (lane == 0) { smean[o] = mean; sscale[o] = bn1_g[v*S2+o] * rsqrtf(vv*(1.f/B) + 1e-5f); }
    }
    __syncthreads();

    for (int i = tid; i < B*S2; i += 512) {
        int o = i % S2;
        su[i] = (su[i] - smean[o]) * sscale[o] + sbeta[o];
    }
    __syncthreads();

    // l2 + ReLU, write k-major
    for (int i = tid; i < S2*B; i += 512) {
        int p = i / B, b = i % B;
        float acc = sb2[p];
        const float* ur = &su[b*S2];
        const float* wr = &sl2[p*S2];
        #pragma unroll
        for (int o = 0; o < S2; ++o) acc = fmaf(ur[o], wr[o], acc);
        g_xT[(v*S2 + p)*B + b] = fmaxf(acc, 0.f);
    }
}

// ---------------------------------------------------------------------------
// Kernel 3: fc1 (800->500) + BN2. grid=100, blockDim=512 (16 warps).
// 16 k-slices of 50. Lane l owns batches 4l..4l+3 (float4, coalesced).
// Slices 8..15 merge into part[slice-8] in a race-free second pass.
#define FPB 5
__global__ void __launch_bounds__(512, 1)
k_fc1(const float* __restrict__ fc1_w, const float* __restrict__ fc1_b,
      const float* __restrict__ bn2_g, const float* __restrict__ bn2_b) {
    __shared__ float sw[FPB*KX];            // 16 KB
    __shared__ float part[8*FPB*B];         // 20 KB
    __shared__ float smean[FPB], sscale[FPB];
    int f0 = blockIdx.x * FPB;
    int tid = threadIdx.x;
    int w = tid >> 5, lane = tid & 31;

    for (int i = tid; i < FPB*KX; i += 512) sw[i] = fc1_w[f0*KX + i];
    __syncthreads();

    float acc[FPB][4];
    #pragma unroll
    for (int ff = 0; ff < FPB; ++ff) {
        float bv = (w == 0) ? fc1_b[f0+ff] : 0.f;
        acc[ff][0] = bv; acc[ff][1] = bv; acc[ff][2] = bv; acc[ff][3] = bv;
    }
    const float4* x4 = reinterpret_cast<const float4*>(g_xT);  // [k][b/4]
    int k0 = w * 50;                      // 16 slices x 50 k
    #pragma unroll 8
    for (int k = k0; k < k0 + 50; ++k) {
        float4 xv = x4[k*32 + lane];
        #pragma unroll
        for (int ff = 0; ff < FPB; ++ff) {
            float wv = sw[ff*KX + k];
            acc[ff][0] = fmaf(wv, xv.x, acc[ff][0]);
            acc[ff][1] = fmaf(wv, xv.y, acc[ff][1]);
            acc[ff][2] = fmaf(wv, xv.z, acc[ff][2]);
            acc[ff][3] = fmaf(wv, xv.w, acc[ff][3]);
        }
    }
    if (w < 8) {
        #pragma unroll
        for (int ff = 0; ff < FPB; ++ff)
            #pragma unroll
            for (int u = 0; u < 4; ++u)
                part[(w*FPB + ff)*B + 4*lane + u] = acc[ff][u];
    }
    __syncthreads();
    if (w >= 8) {                          // slice w adds into part[w-8]: one warp per slot
        #pragma unroll
        for (int ff = 0; ff < FPB; ++ff)
            #pragma unroll
            for (int u = 0; u < 4; ++u)
                part[((w-8)*FPB + ff)*B + 4*lane + u] += acc[ff][u];
    }
    __syncthreads();
    // serial deterministic combine over the 8 merged slices
    for (int i = tid; i < FPB*B; i += 512) {
        float s = part[i];
        #pragma unroll
        for (int ks = 1; ks < 8; ++ks) s += part[ks*FPB*B + i];
        part[i] = s;
    }
    __syncthreads();

    // BN2 stats: warp ff reduces feature ff over batch
    if (w < FPB) {
        float s = 0.f;
        #pragma unroll
        for (int b = lane; b < B; b += 32) s += part[w*B + b];
        s = warpSum(s);
        s = __shfl_sync(0xffffffffu, s, 0);
        float mean = s * (1.f / B);
        float vv = 0.f;
        #pragma unroll
        for (int b = lane; b < B; b += 32) { float d = part[w*B + b] - mean; vv = fmaf(d, d, vv); }
        vv = warpSum(vv);
        if (lane == 0) { smean[w] = mean; sscale[w] = bn2_g[f0+w] * rsqrtf(vv*(1.f/B) + 1e-5f); }
    }
    __syncthreads();

    for (int i = tid; i < FPB*B; i += 512) {
        int ff = i / B, b = i % B;
        g_y1[(f0+ff)*B + b] = (part[i] - smean[ff]) * sscale[ff] + bn2_b[f0+ff];
    }
}

// ---------------------------------------------------------------------------
// Kernel 4: fc2 (500->200). grid=100, blockDim=512 (16 warps).
// 16 k-slices of ~31. Lane l owns batches 4l..4l+3 (float4, coalesced).
#define OPB 2
__global__ void __launch_bounds__(512, 1)
k_fc2(const float* __restrict__ fc2_w, const float* __restrict__ fc2_b,
      float* __restrict__ out) {
    __shared__ float sw[OPB*F1];            // 4 KB
    __shared__ float part[8*OPB*B];         // 8 KB
    int o0 = blockIdx.x * OPB;
    int tid = threadIdx.x;
    int w = tid >> 5, lane = tid & 31;

    for (int i = tid; i < OPB*F1; i += 512) sw[i] = fc2_w[o0*F1 + i];
    __syncthreads();

    float a0[4], a1[4];
    {
        float b0 = (w == 0) ? fc2_b[o0]   : 0.f;
        float b1 = (w == 0) ? fc2_b[o0+1] : 0.f;
        a0[0]=b0; a0[1]=b0; a0[2]=b0; a0[3]=b0;
        a1[0]=b1; a1[1]=b1; a1[2]=b1; a1[3]=b1;
    }
    const float4* y4 = reinterpret_cast<const float4*>(g_y1);  // [f][b/4]
    int fs = (w * F1) / 16, fe = ((w + 1) * F1) / 16;
    #pragma unroll 8
    for (int f = fs; f < fe; ++f) {
        float4 yv = y4[f*32 + lane];
        float w0 = sw[f], w1 = sw[F1 + f];
        a0[0] = fmaf(w0, yv.x, a0[0]); a1[0] = fmaf(w1, yv.x, a1[0]);
        a0[1] = fmaf(w0, yv.y, a0[1]); a1[1] = fmaf(w1, yv.y, a1[1]);
        a0[2] = fmaf(w0, yv.z, a0[2]); a1[2] = fmaf(w1, yv.z, a1[2]);
        a0[3] = fmaf(w0, yv.w, a0[3]); a1[3] = fmaf(w1, yv.w, a1[3]);
    }
    if (w < 8) {
        #pragma unroll
        for (int u = 0; u < 4; ++u) {
            part[(w*OPB + 0)*B + 4*lane + u] = a0[u];
            part[(w*OPB + 1)*B + 4*lane + u] = a1[u];
        }
    }
    __syncthreads();
    if (w >= 8) {
        #pragma unroll
        for (int u = 0; u < 4; ++u) {
            part[((w-8)*OPB + 0)*B + 4*lane + u] += a0[u];
            part[((w-8)*OPB + 1)*B + 4*lane + u] += a1[u];
        }
    }
    __syncthreads();
    // serial combine + store
    for (int i = tid; i < OPB*B; i += 512) {
        float s = part[i];
        #pragma unroll
        for (int ks = 1; ks < 8; ++ks) s += part[ks*OPB*B + i];
        int oo = i / B, b = i % B;
        out[b*F2 + o0 + oo] = s;
    }
}

// ---------------------------------------------------------------------------
extern "C" void kernel_launch(void* const* d_in, const int* in_sizes, int n_in,
                              void* d_out, int out_size) {
    const float* births    = (const float*)d_in[0];
    const float* lifetimes = (const float*)d_in[1];
    const int*   mask      = (const int*)  d_in[2];
    const float* centers   = (const float*)d_in[3];
    const float* sharpness = (const float*)d_in[4];
    const float* w1        = (const float*)d_in[5];
    const float* w2        = (const float*)d_in[6];
    const float* l1_w      = (const float*)d_in[7];
    const float* l1_b      = (const float*)d_in[8];
    const float* bn1_g     = (const float*)d_in[9];
    const float* bn1_b     = (const float*)d_in[10];
    const float* l2_w      = (const float*)d_in[11];
    const float* l2_b      = (const float*)d_in[12];
    const float* fc1_w     = (const float*)d_in[13];
    const float* fc1_b     = (const float*)d_in[14];
    const float* bn2_g     = (const float*)d_in[15];
    const float* bn2_b     = (const float*)d_in[16];
    const float* fc2_w     = (const float*)d_in[17];
    const float* fc2_b     = (const float*)d_in[18];
    float* out = (float*)d_out;

    k_slayer<<<V*B/2, 160>>>(births, lifetimes, mask, centers, sharpness);
    k_mid   <<<V, 512>>>(w1, w2, l1_w, l1_b, bn1_g, bn1_b, l2_w, l2_b);
    k_fc1   <<<F1/FPB, 512>>>(fc1_w, fc1_b, bn2_g, bn2_b);
    k_fc2   <<<F2/OPB, 512>>>(fc2_w, fc2_b, out);
}